// round 15
// baseline (speedup 1.0000x reference)
#include <cuda_runtime.h>
#include <cuda_bf16.h>
#include <cuda_fp16.h>
#include <math.h>
#include <stdint.h>

// ---------------------------------------------------------------------------
// EGNN edge message via warp-level HMMA.
//   Kernel 0: pack W1a/W1b (bf16 hi/lo) + W2/W3 (fp16 hi/lo) fragment tables
//   Kernel 1: P[n] = [ hh[n]@W1a + b1 | hh[n]@W1b ] via HMMA (bf16 x3), fp16
//   Kernel 2 (per 128-edge block, 4 warps x 32 rows):
//     fp16 A tiles, fp16 hi/lo W (2 products), joint-mt W reuse;
//     f16x2 silu (layers 1+2); h2 round-trips through the dead A tile
//     (lossless, frees 32 regs) -> __launch_bounds__(128,5), 20 warps/SM.
// Output: [ radial (E) | trans (3E) | edge_feature (64E) ]
// ---------------------------------------------------------------------------

#define N_MAX_NODES 50048
__device__ __half g_Ph[(size_t)N_MAX_NODES * 128];   // fp16 P table (256B/node)
__device__ float4 g_Xp[N_MAX_NODES];
__device__ uint4  g_WF1A[1024];   // bf16 hi/lo (precompute)
__device__ uint4  g_WF1B[1024];   // bf16 hi/lo (precompute)
__device__ uint4  g_WF2[1024];    // fp16 hi/lo (edge)
__device__ uint4  g_WF3[1024];    // fp16 hi/lo (edge)

__device__ __forceinline__ float tanh_ap(float v) {
    float t;
    asm("tanh.approx.f32 %0, %1;" : "=f"(t) : "f"(v));
    return t;
}
__device__ __forceinline__ float siluf(float v) {
    float t = 0.5f * v;
    return fmaf(t, tanh_ap(t), t);
}
__device__ __forceinline__ uint32_t hadd2u(uint32_t a, uint32_t b) {
    uint32_t d; asm("add.f16x2 %0,%1,%2;" : "=r"(d) : "r"(a), "r"(b)); return d;
}
__device__ __forceinline__ uint32_t hmul2u(uint32_t a, uint32_t b) {
    uint32_t d; asm("mul.f16x2 %0,%1,%2;" : "=r"(d) : "r"(a), "r"(b)); return d;
}
__device__ __forceinline__ uint32_t hfma2u(uint32_t a, uint32_t b, uint32_t c) {
    uint32_t d;
    asm("fma.rn.f16x2 %0,%1,%2,%3;" : "=r"(d) : "r"(a), "r"(b), "r"(c));
    return d;
}
__device__ __forceinline__ uint32_t silu_h2(uint32_t v) {
    uint32_t t = hmul2u(v, 0x38003800u);
    uint32_t th;
    asm("tanh.approx.f16x2 %0, %1;" : "=r"(th) : "r"(t));
    return hfma2u(t, th, t);
}

__device__ __forceinline__ void split_pair_bf(float a, float b,
                                              uint32_t& hi, uint32_t& lo) {
    __nv_bfloat162 h2 = __floats2bfloat162_rn(a, b);
    float ra = a - __bfloat162float(h2.x);
    float rb = b - __bfloat162float(h2.y);
    __nv_bfloat162 l2 = __floats2bfloat162_rn(ra, rb);
    hi = *reinterpret_cast<uint32_t*>(&h2);
    lo = *reinterpret_cast<uint32_t*>(&l2);
}

__device__ __forceinline__ void split_pair_h(float a, float b,
                                             uint32_t& hi, uint32_t& lo) {
    __half2 h2 = __floats2half2_rn(a, b);
    float ra = a - __half2float(__low2half(h2));
    float rb = b - __half2float(__high2half(h2));
    __half2 l2 = __floats2half2_rn(ra, rb);
    hi = *reinterpret_cast<uint32_t*>(&h2);
    lo = *reinterpret_cast<uint32_t*>(&l2);
}

__device__ __forceinline__ uint32_t packh2(float a, float b) {
    __half2 h2 = __floats2half2_rn(a, b);
    return *reinterpret_cast<uint32_t*>(&h2);
}

__device__ __forceinline__ float2 h2f2(uint32_t u) {
    return __half22float2(*reinterpret_cast<__half2*>(&u));
}

// ---------------- Kernel 0: pack mma fragment tables -----------------------
__global__ void __launch_bounds__(128) pack_wf_kernel(
    const float* __restrict__ W1,
    const float* __restrict__ W2, const float* __restrict__ W3)
{
    int idx = blockIdx.x * 128 + threadIdx.x;
    if (idx >= 1024) return;
    int t = idx >> 5, l = idx & 31;
    int kt = t & 3, nt = t >> 2;
    int g = l >> 2, tg = l & 3;
    int k0 = kt * 16 + tg * 2;
    int n = nt * 8 + g;
    #pragma unroll
    for (int tab = 0; tab < 4; tab++) {
        const float* W;
        int roff = 0;
        uint4* dstv;
        if (tab == 0)      { W = W1; roff = 1;  dstv = g_WF1A; }
        else if (tab == 1) { W = W1; roff = 65; dstv = g_WF1B; }
        else if (tab == 2) { W = W2; dstv = g_WF2; }
        else               { W = W3; dstv = g_WF3; }
        float w00 = W[(roff + k0) * 64 + n],     w01 = W[(roff + k0 + 1) * 64 + n];
        float w10 = W[(roff + k0 + 8) * 64 + n], w11 = W[(roff + k0 + 9) * 64 + n];
        uint4 v;
        if (tab < 2) {
            split_pair_bf(w00, w01, v.x, v.z);
            split_pair_bf(w10, w11, v.y, v.w);
        } else {
            split_pair_h(w00, w01, v.x, v.z);
            split_pair_h(w10, w11, v.y, v.w);
        }
        dstv[idx] = v;
    }
}

// ------------------------------ mma helpers ---------------------------------
#define STS32(addr, v0) \
    asm volatile("st.shared.b32 [%0], %1;" :: "r"(addr), "r"(v0) : "memory")
#define STS64(addr, v0, v1) \
    asm volatile("st.shared.v2.b32 [%0], {%1,%2};" \
                 :: "r"(addr), "r"(v0), "r"(v1) : "memory")
#define STS128(addr, v) \
    asm volatile("st.shared.v4.b32 [%0], {%1,%2,%3,%4};" \
                 :: "r"(addr), "r"((v).x), "r"((v).y), "r"((v).z), "r"((v).w) \
                 : "memory")

__device__ __forceinline__ void ldmx4(uint32_t* r, uint32_t addr) {
    asm volatile("ldmatrix.sync.aligned.m8n8.x4.shared.b16 {%0,%1,%2,%3}, [%4];"
        : "=r"(r[0]), "=r"(r[1]), "=r"(r[2]), "=r"(r[3]) : "r"(addr));
}

__device__ __forceinline__ void mma_bf(float* d, const uint32_t* a,
                                       const uint32_t* b) {
    asm volatile(
        "mma.sync.aligned.m16n8k16.row.col.f32.bf16.bf16.f32 "
        "{%0,%1,%2,%3}, {%4,%5,%6,%7}, {%8,%9}, {%0,%1,%2,%3};"
        : "+f"(d[0]), "+f"(d[1]), "+f"(d[2]), "+f"(d[3])
        : "r"(a[0]), "r"(a[1]), "r"(a[2]), "r"(a[3]), "r"(b[0]), "r"(b[1]));
}

__device__ __forceinline__ void mma_h(float* d, const uint32_t* a,
                                      const uint32_t* b) {
    asm volatile(
        "mma.sync.aligned.m16n8k16.row.col.f32.f16.f16.f32 "
        "{%0,%1,%2,%3}, {%4,%5,%6,%7}, {%8,%9}, {%0,%1,%2,%3};"
        : "+f"(d[0]), "+f"(d[1]), "+f"(d[2]), "+f"(d[3])
        : "r"(a[0]), "r"(a[1]), "r"(a[2]), "r"(a[3]), "r"(b[0]), "r"(b[1]));
}

// precompute smem layout (bf16 hi/lo, 128B rows x2)
#define PRE_AHI  0
#define PRE_ALO  16384
#define PRE_VEC  32768
#define SMEM_PRE 33792

// edge smem layout: fp16 A tile [0,16K), vectors
#define EDG_A    0
#define EDG_VEC  16384
#define SMEM_EDG 17408

// ---------------- Kernel 1: per-node projection via HMMA --------------------
__global__ void __launch_bounds__(128) precompute_mma_kernel(
    const float* __restrict__ x,
    const float* __restrict__ hh, const float* __restrict__ b1, int n_nodes)
{
    extern __shared__ char sm[];
    uint32_t smb = (uint32_t)__cvta_generic_to_shared(sm);
    int tid = threadIdx.x;
    int lane = tid & 31;
    int warp = tid >> 5;
    int m0 = warp * 32;
    int gid = lane >> 2, tig = lane & 3;

    float* b1v = (float*)(sm + PRE_VEC);
    if (tid < 64) b1v[tid] = b1[tid];

    int nb = blockIdx.x * 128;
    int node = nb + m0 + lane;
    if (node < n_nodes) {
        const float* xp = x + 3 * node;
        g_Xp[node] = make_float4(xp[0], xp[1], xp[2], 0.f);
    }

    uint32_t aHi = smb + PRE_AHI, aLo = smb + PRE_ALO;

    {
        int g = lane >> 3, c = lane & 7;
        #pragma unroll
        for (int j = 0; j < 8; j++) {
            int row = m0 + j * 4 + g;
            int n = nb + row;
            uint32_t rowHi = aHi + (uint32_t)row * 128;
            uint32_t rowLo = aLo + (uint32_t)row * 128;
            int rx = row & 7;
            #pragma unroll
            for (int half = 0; half < 2; half++) {
                int q = half * 8 + c;
                float4 a = (n < n_nodes)
                    ? *(const float4*)(hh + (size_t)n * 64 + q * 4)
                    : make_float4(0.f, 0.f, 0.f, 0.f);
                uint32_t hi0, lo0, hi1, lo1;
                split_pair_bf(a.x, a.y, hi0, lo0);
                split_pair_bf(a.z, a.w, hi1, lo1);
                uint32_t off = (uint32_t)((((q >> 1) ^ rx) << 4) + (q & 1) * 8);
                STS64(rowHi + off, hi0, hi1);
                STS64(rowLo + off, lo0, lo1);
            }
        }
    }
    __syncthreads();

    int Lmat = lane >> 3;
    #pragma unroll 1
    for (int mt = 0; mt < 2; mt++) {
        uint32_t AH[4][4], AL[4][4];
        #pragma unroll
        for (int kt = 0; kt < 4; kt++) {
            int rr = m0 + mt * 16 + (Lmat & 1) * 8 + (lane & 7);
            int chunk = kt * 2 + (Lmat >> 1);
            uint32_t off = (uint32_t)(rr * 128 + ((chunk ^ (rr & 7)) << 4));
            ldmx4(AH[kt], aHi + off);
            ldmx4(AL[kt], aLo + off);
        }
        int r0 = m0 + mt * 16 + gid;
        int r1 = r0 + 8;
        int n0 = nb + r0, n1 = nb + r1;

        #pragma unroll 1
        for (int half = 0; half < 2; half++) {
            const uint4* WF = half ? g_WF1B : g_WF1A;
            float D[8][4];
            #pragma unroll
            for (int nt = 0; nt < 8; nt++) {
                float b0 = half ? 0.f : b1v[nt * 8 + tig * 2];
                float b1x = half ? 0.f : b1v[nt * 8 + tig * 2 + 1];
                D[nt][0] = b0; D[nt][1] = b1x;
                D[nt][2] = b0; D[nt][3] = b1x;
            }
            #pragma unroll
            for (int nt = 0; nt < 8; nt++) {
                #pragma unroll
                for (int kt = 0; kt < 4; kt++) {
                    uint4 w = __ldg(&WF[(nt * 4 + kt) * 32 + lane]);
                    uint32_t bh[2] = { w.x, w.y };
                    uint32_t bl[2] = { w.z, w.w };
                    mma_bf(D[nt], AH[kt], bh);
                    mma_bf(D[nt], AH[kt], bl);
                    mma_bf(D[nt], AL[kt], bh);
                }
            }
            #pragma unroll
            for (int nt = 0; nt < 8; nt++) {
                int col = half * 64 + nt * 8 + tig * 2;
                if (n0 < n_nodes)
                    *(uint32_t*)((char*)g_Ph + (size_t)n0 * 256 + col * 2) =
                        packh2(D[nt][0], D[nt][1]);
                if (n1 < n_nodes)
                    *(uint32_t*)((char*)g_Ph + (size_t)n1 * 256 + col * 2) =
                        packh2(D[nt][2], D[nt][3]);
            }
        }
    }
}

// ---------------------------- Kernel 2: edges -------------------------------
__global__ void __launch_bounds__(128, 5) edge_mma_kernel(
    const int* __restrict__ src, const int* __restrict__ dst,
    const float* __restrict__ W1,
    const float* __restrict__ b2, const float* __restrict__ b3,
    const float* __restrict__ W4,
    float* __restrict__ out, int E)
{
    extern __shared__ char sm[];
    uint32_t smb = (uint32_t)__cvta_generic_to_shared(sm);
    int tid = threadIdx.x;
    int lane = tid & 31;
    int warp = tid >> 5;
    int m0 = warp * 32;
    int gid = lane >> 2, tig = lane & 3;

    uint32_t* w1h = (uint32_t*)(sm + EDG_VEC);        // packed f16x2 W1 row0
    float* b2v = (float*)(sm + EDG_VEC + 256);
    float* b3v = (float*)(sm + EDG_VEC + 512);
    float* w4v = (float*)(sm + EDG_VEC + 768);
    if (tid < 32) w1h[tid] = packh2(W1[2 * tid], W1[2 * tid + 1]);
    if (tid < 64) {
        b2v[tid] = b2[tid];
        b3v[tid] = b3[tid];
        w4v[tid] = W4[tid];
    }
    __syncthreads();

    int base = blockIdx.x * 128;
    int e = base + m0 + lane;
    bool valid = e < E;
    int s = 0, dn = 0;
    if (valid) { s = src[e]; dn = dst[e]; }
    float4 xs = g_Xp[s], xd = g_Xp[dn];
    float cx = xs.x - xd.x, cy = xs.y - xd.y, cz = xs.z - xd.z;
    float r = cx * cx + cy * cy + cz * cz;
    if (valid) out[e] = r;

    uint32_t aT = smb + EDG_A;

    // ---- layer 1: fp16 P gather + f16x2 silu -> A tile (no conversions) ----
    {
        int g = lane >> 3, c = lane & 7;
        const char* Pb = (const char*)g_Ph;
        uint32_t wv0 = w1h[4 * c], wv1 = w1h[4 * c + 1],
                 wv2 = w1h[4 * c + 2], wv3 = w1h[4 * c + 3];
        #pragma unroll
        for (int j = 0; j < 8; j++) {
            int sl = j * 4 + g;
            int sE = __shfl_sync(0xffffffffu, s,  sl);
            int dE = __shfl_sync(0xffffffffu, dn, sl);
            float rE = __shfl_sync(0xffffffffu, r, sl);
            uint32_t rE2 = packh2(rE, rE);
            int row = m0 + j * 4 + g;
            uint32_t rowB = aT + (uint32_t)row * 128;
            int rx = row & 7;
            uint4 av = *(const uint4*)(Pb + (size_t)sE * 256 + c * 16);
            uint4 bv = *(const uint4*)(Pb + (size_t)dE * 256 + 128 + c * 16);
            uint4 hv;
            hv.x = silu_h2(hfma2u(rE2, wv0, hadd2u(av.x, bv.x)));
            hv.y = silu_h2(hfma2u(rE2, wv1, hadd2u(av.y, bv.y)));
            hv.z = silu_h2(hfma2u(rE2, wv2, hadd2u(av.z, bv.z)));
            hv.w = silu_h2(hfma2u(rE2, wv3, hadd2u(av.w, bv.w)));
            STS128(rowB + (uint32_t)(((c ^ rx) << 4)), hv);
        }
    }
    __syncwarp();

    float* fout = out + (size_t)4 * E;
    float* outT = out + E;
    int Lmat = lane >> 3;

    // ---- A fragments for both 16-row halves (fp16 single) ----
    uint32_t AH[2][4][4];
    #pragma unroll
    for (int mt = 0; mt < 2; mt++) {
        #pragma unroll
        for (int kt = 0; kt < 4; kt++) {
            int rr = m0 + mt * 16 + (Lmat & 1) * 8 + (lane & 7);
            int chunk = kt * 2 + (Lmat >> 1);
            uint32_t off = (uint32_t)(rr * 128 + ((chunk ^ (rr & 7)) << 4));
            ldmx4(AH[mt][kt], aT + off);
        }
    }
    __syncwarp();   // warp's own A rows consumed; safe to overwrite with h2

    // ---- layer 2: joint-mt, nt pairs; h2 -> features + back into A tile ----
    #pragma unroll
    for (int ntp = 0; ntp < 4; ntp++) {
        float D[2][2][4];
        #pragma unroll
        for (int nn = 0; nn < 2; nn++) {
            int nt = 2 * ntp + nn;
            float b0 = b2v[nt * 8 + tig * 2];
            float b1 = b2v[nt * 8 + tig * 2 + 1];
            #pragma unroll
            for (int mt = 0; mt < 2; mt++) {
                D[mt][nn][0] = b0; D[mt][nn][1] = b1;
                D[mt][nn][2] = b0; D[mt][nn][3] = b1;
            }
        }
        #pragma unroll
        for (int nn = 0; nn < 2; nn++) {
            int nt = 2 * ntp + nn;
            #pragma unroll
            for (int kt = 0; kt < 4; kt++) {
                uint4 w = __ldg(&g_WF2[(nt * 4 + kt) * 32 + lane]);
                uint32_t bh[2] = { w.x, w.y };
                uint32_t bl[2] = { w.z, w.w };
                mma_h(D[0][nn], AH[0][kt], bh);
                mma_h(D[0][nn], AH[0][kt], bl);
                mma_h(D[1][nn], AH[1][kt], bh);
                mma_h(D[1][nn], AH[1][kt], bl);
            }
        }
        #pragma unroll
        for (int mt = 0; mt < 2; mt++) {
            int r0 = m0 + mt * 16 + gid;
            int r1 = r0 + 8;
            int e0 = base + r0, e1 = base + r1;
            uint32_t rowB0 = aT + (uint32_t)r0 * 128;
            uint32_t rowB1 = aT + (uint32_t)r1 * 128;
            #pragma unroll
            for (int nn = 0; nn < 2; nn++) {
                int nt = 2 * ntp + nn;
                uint32_t s01 = silu_h2(packh2(D[mt][nn][0], D[mt][nn][1]));
                uint32_t s23 = silu_h2(packh2(D[mt][nn][2], D[mt][nn][3]));
                int col = nt * 8 + tig * 2;
                if (e0 < E) {
                    float2 f = h2f2(s01);
                    *(float2*)(fout + (size_t)e0 * 64 + col) = f;
                }
                if (e1 < E) {
                    float2 f = h2f2(s23);
                    *(float2*)(fout + (size_t)e1 * 64 + col) = f;
                }
                // write h2 (already fp16) back into the A tile, swizzled
                uint32_t o0 = (uint32_t)(((nt ^ (r0 & 7)) << 4) + tig * 4);
                uint32_t o1 = (uint32_t)(((nt ^ (r1 & 7)) << 4) + tig * 4);
                STS32(rowB0 + o0, s01);
                STS32(rowB1 + o1, s23);
            }
        }
    }
    __syncwarp();

    // ---- layer 3: A3 fragments reloaded from the A tile via ldmatrix ----
    float dv[2][2] = { {0.f, 0.f}, {0.f, 0.f} };
    {
        uint32_t A3[2][4][4];
        #pragma unroll
        for (int mt = 0; mt < 2; mt++) {
            #pragma unroll
            for (int kt = 0; kt < 4; kt++) {
                int rr = m0 + mt * 16 + (Lmat & 1) * 8 + (lane & 7);
                int chunk = kt * 2 + (Lmat >> 1);
                uint32_t off = (uint32_t)(rr * 128 + ((chunk ^ (rr & 7)) << 4));
                ldmx4(A3[mt][kt], aT + off);
            }
        }
        #pragma unroll
        for (int ntp = 0; ntp < 4; ntp++) {
            float D[2][2][4];
            #pragma unroll
            for (int nn = 0; nn < 2; nn++) {
                int nt = 2 * ntp + nn;
                float b0 = b3v[nt * 8 + tig * 2];
                float b1 = b3v[nt * 8 + tig * 2 + 1];
                #pragma unroll
                for (int mt = 0; mt < 2; mt++) {
                    D[mt][nn][0] = b0; D[mt][nn][1] = b1;
                    D[mt][nn][2] = b0; D[mt][nn][3] = b1;
                }
            }
            #pragma unroll
            for (int nn = 0; nn < 2; nn++) {
                int nt = 2 * ntp + nn;
                #pragma unroll
                for (int kt = 0; kt < 4; kt++) {
                    uint4 w = __ldg(&g_WF3[(nt * 4 + kt) * 32 + lane]);
                    uint32_t bh[2] = { w.x, w.y };
                    uint32_t bl[2] = { w.z, w.w };
                    mma_h(D[0][nn], A3[0][kt], bh);
                    mma_h(D[0][nn], A3[0][kt], bl);
                    mma_h(D[1][nn], A3[1][kt], bh);
                    mma_h(D[1][nn], A3[1][kt], bl);
                }
            }
            #pragma unroll
            for (int mt = 0; mt < 2; mt++) {
                #pragma unroll
                for (int nn = 0; nn < 2; nn++) {
                    int nt = 2 * ntp + nn;
                    int col = nt * 8 + tig * 2;
                    float wa = w4v[col], wb = w4v[col + 1];
                    dv[mt][0] = fmaf(siluf(D[mt][nn][0]), wa,
                                fmaf(siluf(D[mt][nn][1]), wb, dv[mt][0]));
                    dv[mt][1] = fmaf(siluf(D[mt][nn][2]), wa,
                                fmaf(siluf(D[mt][nn][3]), wb, dv[mt][1]));
                }
            }
        }
    }

    // ---- trans output ----
    #pragma unroll
    for (int mt = 0; mt < 2; mt++) {
        float d0 = dv[mt][0], d1 = dv[mt][1];
        d0 += __shfl_xor_sync(0xffffffffu, d0, 1);
        d0 += __shfl_xor_sync(0xffffffffu, d0, 2);
        d1 += __shfl_xor_sync(0xffffffffu, d1, 1);
        d1 += __shfl_xor_sync(0xffffffffu, d1, 2);
        int rw = mt * 16 + (tig & 1) * 8 + gid;
        float dsel = (tig & 1) ? d1 : d0;
        float rr  = __shfl_sync(0xffffffffu, r,  rw);
        float cxx = __shfl_sync(0xffffffffu, cx, rw);
        float cyy = __shfl_sync(0xffffffffu, cy, rw);
        float czz = __shfl_sync(0xffffffffu, cz, rw);
        int ee = base + m0 + rw;
        float msc = __fdividef(tanh_ap(dsel), sqrtf(rr) + 1e-8f);
        if (tig < 2 && ee < E) {
            outT[3 * ee + 0] = cxx * msc;
            outT[3 * ee + 1] = cyy * msc;
            outT[3 * ee + 2] = czz * msc;
        }
    }
}

extern "C" void kernel_launch(void* const* d_in, const int* in_sizes, int n_in,
                              void* d_out, int out_size) {
    const float* x  = (const float*)d_in[0];
    const float* hh = (const float*)d_in[1];
    const int* src  = (const int*)d_in[2];
    const int* dst  = (const int*)d_in[3];
    const float* W1 = (const float*)d_in[4];
    const float* b1 = (const float*)d_in[5];
    const float* W2 = (const float*)d_in[6];
    const float* b2 = (const float*)d_in[7];
    const float* W3 = (const float*)d_in[8];
    const float* b3 = (const float*)d_in[9];
    const float* W4 = (const float*)d_in[10];
    int N = in_sizes[0] / 3;
    int E = in_sizes[2];
    float* out = (float*)d_out;

    cudaFuncSetAttribute(precompute_mma_kernel,
                         cudaFuncAttributeMaxDynamicSharedMemorySize, SMEM_PRE);
    cudaFuncSetAttribute(edge_mma_kernel,
                         cudaFuncAttributeMaxDynamicSharedMemorySize, SMEM_EDG);

    pack_wf_kernel<<<8, 128>>>(W1, W2, W3);

    int pblocks = (N + 127) / 128;
    precompute_mma_kernel<<<pblocks, 128, SMEM_PRE>>>(x, hh, b1, N);

    int eblocks = (E + 127) / 128;
    edge_mma_kernel<<<eblocks, 128, SMEM_EDG>>>(src, dst, W1, b2, b3,
                                                W4, out, E);
    (void)n_in; (void)out_size;
}

// round 16
// speedup vs baseline: 1.0867x; 1.0867x over previous
#include <cuda_runtime.h>
#include <cuda_bf16.h>
#include <cuda_fp16.h>
#include <math.h>
#include <stdint.h>

// ---------------------------------------------------------------------------
// EGNN edge message via warp-level HMMA.  (r14 base + pipelined layer-1 gather)
//   Kernel 0: pack W1a/W1b (bf16 hi/lo) + W2/W3 (fp16 hi/lo) fragment tables
//   Kernel 1: P[n] = [ hh[n]@W1a + b1 | hh[n]@W1b ] via HMMA (bf16 x3), fp16
//   Kernel 2 (per 128-edge block, 4 warps x 32 rows):
//     fp16 A tiles, fp16 hi/lo W (2 products), joint-mt W reuse;
//     layer-1 gather software-pipelined (double-buffered LDG.128);
//     f16x2 silu (layers 1+2); layer-3 epilogue fp32.
// Output: [ radial (E) | trans (3E) | edge_feature (64E) ]
// ---------------------------------------------------------------------------

#define N_MAX_NODES 50048
__device__ __half g_Ph[(size_t)N_MAX_NODES * 128];   // fp16 P table (256B/node)
__device__ float4 g_Xp[N_MAX_NODES];
__device__ uint4  g_WF1A[1024];   // bf16 hi/lo (precompute)
__device__ uint4  g_WF1B[1024];   // bf16 hi/lo (precompute)
__device__ uint4  g_WF2[1024];    // fp16 hi/lo (edge)
__device__ uint4  g_WF3[1024];    // fp16 hi/lo (edge)

__device__ __forceinline__ float tanh_ap(float v) {
    float t;
    asm("tanh.approx.f32 %0, %1;" : "=f"(t) : "f"(v));
    return t;
}
__device__ __forceinline__ float siluf(float v) {
    float t = 0.5f * v;
    return fmaf(t, tanh_ap(t), t);
}
__device__ __forceinline__ uint32_t hadd2u(uint32_t a, uint32_t b) {
    uint32_t d; asm("add.f16x2 %0,%1,%2;" : "=r"(d) : "r"(a), "r"(b)); return d;
}
__device__ __forceinline__ uint32_t hmul2u(uint32_t a, uint32_t b) {
    uint32_t d; asm("mul.f16x2 %0,%1,%2;" : "=r"(d) : "r"(a), "r"(b)); return d;
}
__device__ __forceinline__ uint32_t hfma2u(uint32_t a, uint32_t b, uint32_t c) {
    uint32_t d;
    asm("fma.rn.f16x2 %0,%1,%2,%3;" : "=r"(d) : "r"(a), "r"(b), "r"(c));
    return d;
}
__device__ __forceinline__ uint32_t silu_h2(uint32_t v) {
    uint32_t t = hmul2u(v, 0x38003800u);
    uint32_t th;
    asm("tanh.approx.f16x2 %0, %1;" : "=r"(th) : "r"(t));
    return hfma2u(t, th, t);
}

__device__ __forceinline__ void split_pair_bf(float a, float b,
                                              uint32_t& hi, uint32_t& lo) {
    __nv_bfloat162 h2 = __floats2bfloat162_rn(a, b);
    float ra = a - __bfloat162float(h2.x);
    float rb = b - __bfloat162float(h2.y);
    __nv_bfloat162 l2 = __floats2bfloat162_rn(ra, rb);
    hi = *reinterpret_cast<uint32_t*>(&h2);
    lo = *reinterpret_cast<uint32_t*>(&l2);
}

__device__ __forceinline__ void split_pair_h(float a, float b,
                                             uint32_t& hi, uint32_t& lo) {
    __half2 h2 = __floats2half2_rn(a, b);
    float ra = a - __half2float(__low2half(h2));
    float rb = b - __half2float(__high2half(h2));
    __half2 l2 = __floats2half2_rn(ra, rb);
    hi = *reinterpret_cast<uint32_t*>(&h2);
    lo = *reinterpret_cast<uint32_t*>(&l2);
}

__device__ __forceinline__ uint32_t packh2(float a, float b) {
    __half2 h2 = __floats2half2_rn(a, b);
    return *reinterpret_cast<uint32_t*>(&h2);
}

__device__ __forceinline__ float2 h2f2(uint32_t u) {
    return __half22float2(*reinterpret_cast<__half2*>(&u));
}

// ---------------- Kernel 0: pack mma fragment tables -----------------------
__global__ void __launch_bounds__(128) pack_wf_kernel(
    const float* __restrict__ W1,
    const float* __restrict__ W2, const float* __restrict__ W3)
{
    int idx = blockIdx.x * 128 + threadIdx.x;
    if (idx >= 1024) return;
    int t = idx >> 5, l = idx & 31;
    int kt = t & 3, nt = t >> 2;
    int g = l >> 2, tg = l & 3;
    int k0 = kt * 16 + tg * 2;
    int n = nt * 8 + g;
    #pragma unroll
    for (int tab = 0; tab < 4; tab++) {
        const float* W;
        int roff = 0;
        uint4* dstv;
        if (tab == 0)      { W = W1; roff = 1;  dstv = g_WF1A; }
        else if (tab == 1) { W = W1; roff = 65; dstv = g_WF1B; }
        else if (tab == 2) { W = W2; dstv = g_WF2; }
        else               { W = W3; dstv = g_WF3; }
        float w00 = W[(roff + k0) * 64 + n],     w01 = W[(roff + k0 + 1) * 64 + n];
        float w10 = W[(roff + k0 + 8) * 64 + n], w11 = W[(roff + k0 + 9) * 64 + n];
        uint4 v;
        if (tab < 2) {
            split_pair_bf(w00, w01, v.x, v.z);
            split_pair_bf(w10, w11, v.y, v.w);
        } else {
            split_pair_h(w00, w01, v.x, v.z);
            split_pair_h(w10, w11, v.y, v.w);
        }
        dstv[idx] = v;
    }
}

// ------------------------------ mma helpers ---------------------------------
#define STS64(addr, v0, v1) \
    asm volatile("st.shared.v2.b32 [%0], {%1,%2};" \
                 :: "r"(addr), "r"(v0), "r"(v1) : "memory")
#define STS128(addr, v) \
    asm volatile("st.shared.v4.b32 [%0], {%1,%2,%3,%4};" \
                 :: "r"(addr), "r"((v).x), "r"((v).y), "r"((v).z), "r"((v).w) \
                 : "memory")

__device__ __forceinline__ void ldmx4(uint32_t* r, uint32_t addr) {
    asm volatile("ldmatrix.sync.aligned.m8n8.x4.shared.b16 {%0,%1,%2,%3}, [%4];"
        : "=r"(r[0]), "=r"(r[1]), "=r"(r[2]), "=r"(r[3]) : "r"(addr));
}

__device__ __forceinline__ void mma_bf(float* d, const uint32_t* a,
                                       const uint32_t* b) {
    asm volatile(
        "mma.sync.aligned.m16n8k16.row.col.f32.bf16.bf16.f32 "
        "{%0,%1,%2,%3}, {%4,%5,%6,%7}, {%8,%9}, {%0,%1,%2,%3};"
        : "+f"(d[0]), "+f"(d[1]), "+f"(d[2]), "+f"(d[3])
        : "r"(a[0]), "r"(a[1]), "r"(a[2]), "r"(a[3]), "r"(b[0]), "r"(b[1]));
}

__device__ __forceinline__ void mma_h(float* d, const uint32_t* a,
                                      const uint32_t* b) {
    asm volatile(
        "mma.sync.aligned.m16n8k16.row.col.f32.f16.f16.f32 "
        "{%0,%1,%2,%3}, {%4,%5,%6,%7}, {%8,%9}, {%0,%1,%2,%3};"
        : "+f"(d[0]), "+f"(d[1]), "+f"(d[2]), "+f"(d[3])
        : "r"(a[0]), "r"(a[1]), "r"(a[2]), "r"(a[3]), "r"(b[0]), "r"(b[1]));
}

// precompute smem layout (bf16 hi/lo, 128B rows x2)
#define PRE_AHI  0
#define PRE_ALO  16384
#define PRE_VEC  32768
#define SMEM_PRE 33792

// edge smem layout: fp16 A tile [0,16K), vectors
#define EDG_A    0
#define EDG_VEC  16384
#define SMEM_EDG 17408

// ---------------- Kernel 1: per-node projection via HMMA --------------------
__global__ void __launch_bounds__(128) precompute_mma_kernel(
    const float* __restrict__ x,
    const float* __restrict__ hh, const float* __restrict__ b1, int n_nodes)
{
    extern __shared__ char sm[];
    uint32_t smb = (uint32_t)__cvta_generic_to_shared(sm);
    int tid = threadIdx.x;
    int lane = tid & 31;
    int warp = tid >> 5;
    int m0 = warp * 32;
    int gid = lane >> 2, tig = lane & 3;

    float* b1v = (float*)(sm + PRE_VEC);
    if (tid < 64) b1v[tid] = b1[tid];

    int nb = blockIdx.x * 128;
    int node = nb + m0 + lane;
    if (node < n_nodes) {
        const float* xp = x + 3 * node;
        g_Xp[node] = make_float4(xp[0], xp[1], xp[2], 0.f);
    }

    uint32_t aHi = smb + PRE_AHI, aLo = smb + PRE_ALO;

    {
        int g = lane >> 3, c = lane & 7;
        #pragma unroll
        for (int j = 0; j < 8; j++) {
            int row = m0 + j * 4 + g;
            int n = nb + row;
            uint32_t rowHi = aHi + (uint32_t)row * 128;
            uint32_t rowLo = aLo + (uint32_t)row * 128;
            int rx = row & 7;
            #pragma unroll
            for (int half = 0; half < 2; half++) {
                int q = half * 8 + c;
                float4 a = (n < n_nodes)
                    ? *(const float4*)(hh + (size_t)n * 64 + q * 4)
                    : make_float4(0.f, 0.f, 0.f, 0.f);
                uint32_t hi0, lo0, hi1, lo1;
                split_pair_bf(a.x, a.y, hi0, lo0);
                split_pair_bf(a.z, a.w, hi1, lo1);
                uint32_t off = (uint32_t)((((q >> 1) ^ rx) << 4) + (q & 1) * 8);
                STS64(rowHi + off, hi0, hi1);
                STS64(rowLo + off, lo0, lo1);
            }
        }
    }
    __syncthreads();

    int Lmat = lane >> 3;
    #pragma unroll 1
    for (int mt = 0; mt < 2; mt++) {
        uint32_t AH[4][4], AL[4][4];
        #pragma unroll
        for (int kt = 0; kt < 4; kt++) {
            int rr = m0 + mt * 16 + (Lmat & 1) * 8 + (lane & 7);
            int chunk = kt * 2 + (Lmat >> 1);
            uint32_t off = (uint32_t)(rr * 128 + ((chunk ^ (rr & 7)) << 4));
            ldmx4(AH[kt], aHi + off);
            ldmx4(AL[kt], aLo + off);
        }
        int r0 = m0 + mt * 16 + gid;
        int r1 = r0 + 8;
        int n0 = nb + r0, n1 = nb + r1;

        #pragma unroll 1
        for (int half = 0; half < 2; half++) {
            const uint4* WF = half ? g_WF1B : g_WF1A;
            float D[8][4];
            #pragma unroll
            for (int nt = 0; nt < 8; nt++) {
                float b0 = half ? 0.f : b1v[nt * 8 + tig * 2];
                float b1x = half ? 0.f : b1v[nt * 8 + tig * 2 + 1];
                D[nt][0] = b0; D[nt][1] = b1x;
                D[nt][2] = b0; D[nt][3] = b1x;
            }
            #pragma unroll
            for (int nt = 0; nt < 8; nt++) {
                #pragma unroll
                for (int kt = 0; kt < 4; kt++) {
                    uint4 w = __ldg(&WF[(nt * 4 + kt) * 32 + lane]);
                    uint32_t bh[2] = { w.x, w.y };
                    uint32_t bl[2] = { w.z, w.w };
                    mma_bf(D[nt], AH[kt], bh);
                    mma_bf(D[nt], AH[kt], bl);
                    mma_bf(D[nt], AL[kt], bh);
                }
            }
            #pragma unroll
            for (int nt = 0; nt < 8; nt++) {
                int col = half * 64 + nt * 8 + tig * 2;
                if (n0 < n_nodes)
                    *(uint32_t*)((char*)g_Ph + (size_t)n0 * 256 + col * 2) =
                        packh2(D[nt][0], D[nt][1]);
                if (n1 < n_nodes)
                    *(uint32_t*)((char*)g_Ph + (size_t)n1 * 256 + col * 2) =
                        packh2(D[nt][2], D[nt][3]);
            }
        }
    }
}

// ---------------------------- Kernel 2: edges -------------------------------
__global__ void __launch_bounds__(128, 4) edge_mma_kernel(
    const int* __restrict__ src, const int* __restrict__ dst,
    const float* __restrict__ W1,
    const float* __restrict__ b2, const float* __restrict__ b3,
    const float* __restrict__ W4,
    float* __restrict__ out, int E)
{
    extern __shared__ char sm[];
    uint32_t smb = (uint32_t)__cvta_generic_to_shared(sm);
    int tid = threadIdx.x;
    int lane = tid & 31;
    int warp = tid >> 5;
    int m0 = warp * 32;
    int gid = lane >> 2, tig = lane & 3;

    uint32_t* w1h = (uint32_t*)(sm + EDG_VEC);        // packed f16x2 W1 row0
    float* b2v = (float*)(sm + EDG_VEC + 256);
    float* b3v = (float*)(sm + EDG_VEC + 512);
    float* w4v = (float*)(sm + EDG_VEC + 768);
    if (tid < 32) w1h[tid] = packh2(W1[2 * tid], W1[2 * tid + 1]);
    if (tid < 64) {
        b2v[tid] = b2[tid];
        b3v[tid] = b3[tid];
        w4v[tid] = W4[tid];
    }
    __syncthreads();

    int base = blockIdx.x * 128;
    int e = base + m0 + lane;
    bool valid = e < E;
    int s = 0, dn = 0;
    if (valid) { s = src[e]; dn = dst[e]; }
    float4 xs = g_Xp[s], xd = g_Xp[dn];
    float cx = xs.x - xd.x, cy = xs.y - xd.y, cz = xs.z - xd.z;
    float r = cx * cx + cy * cy + cz * cz;
    if (valid) out[e] = r;

    uint32_t aT = smb + EDG_A;

    // ---- layer 1: pipelined fp16 P gather + f16x2 silu -> A tile ----
    {
        int g = lane >> 3, c = lane & 7;
        const char* Pb = (const char*)g_Ph;
        uint32_t wv0 = w1h[4 * c], wv1 = w1h[4 * c + 1],
                 wv2 = w1h[4 * c + 2], wv3 = w1h[4 * c + 3];

        // prologue: issue j=0 loads
        int sE = __shfl_sync(0xffffffffu, s,  g);
        int dE = __shfl_sync(0xffffffffu, dn, g);
        float rE = __shfl_sync(0xffffffffu, r, g);
        uint4 av = *(const uint4*)(Pb + (size_t)sE * 256 + c * 16);
        uint4 bv = *(const uint4*)(Pb + (size_t)dE * 256 + 128 + c * 16);

        #pragma unroll
        for (int j = 0; j < 8; j++) {
            // prefetch j+1 before consuming j
            uint4 av2, bv2;
            float rEn = 0.f;
            if (j < 7) {
                int sl = (j + 1) * 4 + g;
                int sN = __shfl_sync(0xffffffffu, s,  sl);
                int dN = __shfl_sync(0xffffffffu, dn, sl);
                rEn = __shfl_sync(0xffffffffu, r, sl);
                av2 = *(const uint4*)(Pb + (size_t)sN * 256 + c * 16);
                bv2 = *(const uint4*)(Pb + (size_t)dN * 256 + 128 + c * 16);
            }
            uint32_t rE2 = packh2(rE, rE);
            int row = m0 + j * 4 + g;
            uint32_t rowB = aT + (uint32_t)row * 128;
            int rx = row & 7;
            uint4 hv;
            hv.x = silu_h2(hfma2u(rE2, wv0, hadd2u(av.x, bv.x)));
            hv.y = silu_h2(hfma2u(rE2, wv1, hadd2u(av.y, bv.y)));
            hv.z = silu_h2(hfma2u(rE2, wv2, hadd2u(av.z, bv.z)));
            hv.w = silu_h2(hfma2u(rE2, wv3, hadd2u(av.w, bv.w)));
            STS128(rowB + (uint32_t)(((c ^ rx) << 4)), hv);
            av = av2; bv = bv2; rE = rEn;
        }
    }
    __syncwarp();

    float* fout = out + (size_t)4 * E;
    float* outT = out + E;
    int Lmat = lane >> 3;

    // ---- A fragments for both 16-row halves (fp16 single) ----
    uint32_t AH[2][4][4];
    #pragma unroll
    for (int mt = 0; mt < 2; mt++) {
        #pragma unroll
        for (int kt = 0; kt < 4; kt++) {
            int rr = m0 + mt * 16 + (Lmat & 1) * 8 + (lane & 7);
            int chunk = kt * 2 + (Lmat >> 1);
            uint32_t off = (uint32_t)(rr * 128 + ((chunk ^ (rr & 7)) << 4));
            ldmx4(AH[mt][kt], aT + off);
        }
    }

    // ---- layer 2: joint-mt, nt pairs, W fetched once; f16x2 silu epilogue ----
    uint32_t A3H[2][4][4];
    #pragma unroll
    for (int ntp = 0; ntp < 4; ntp++) {
        float D[2][2][4];
        #pragma unroll
        for (int nn = 0; nn < 2; nn++) {
            int nt = 2 * ntp + nn;
            float b0 = b2v[nt * 8 + tig * 2];
            float b1 = b2v[nt * 8 + tig * 2 + 1];
            #pragma unroll
            for (int mt = 0; mt < 2; mt++) {
                D[mt][nn][0] = b0; D[mt][nn][1] = b1;
                D[mt][nn][2] = b0; D[mt][nn][3] = b1;
            }
        }
        #pragma unroll
        for (int nn = 0; nn < 2; nn++) {
            int nt = 2 * ntp + nn;
            #pragma unroll
            for (int kt = 0; kt < 4; kt++) {
                uint4 w = __ldg(&g_WF2[(nt * 4 + kt) * 32 + lane]);
                uint32_t bh[2] = { w.x, w.y };
                uint32_t bl[2] = { w.z, w.w };
                mma_h(D[0][nn], AH[0][kt], bh);
                mma_h(D[0][nn], AH[0][kt], bl);
                mma_h(D[1][nn], AH[1][kt], bh);
                mma_h(D[1][nn], AH[1][kt], bl);
            }
        }
        #pragma unroll
        for (int mt = 0; mt < 2; mt++) {
            int r0 = m0 + mt * 16 + gid;
            int r1 = r0 + 8;
            int e0 = base + r0, e1 = base + r1;
            #pragma unroll
            for (int nn = 0; nn < 2; nn++) {
                int nt = 2 * ntp + nn;
                uint32_t s01 = silu_h2(packh2(D[mt][nn][0], D[mt][nn][1]));
                uint32_t s23 = silu_h2(packh2(D[mt][nn][2], D[mt][nn][3]));
                int col = nt * 8 + tig * 2;
                if (e0 < E) {
                    float2 f = h2f2(s01);
                    *(float2*)(fout + (size_t)e0 * 64 + col) = f;
                }
                if (e1 < E) {
                    float2 f = h2f2(s23);
                    *(float2*)(fout + (size_t)e1 * 64 + col) = f;
                }
                A3H[mt][ntp][nn * 2 + 0] = s01;
                A3H[mt][ntp][nn * 2 + 1] = s23;
            }
        }
    }

    // ---- layer 3: joint-mt, dv accumulated per nt pair (fp32 epilogue) ----
    float dv[2][2] = { {0.f, 0.f}, {0.f, 0.f} };
    #pragma unroll
    for (int ntp = 0; ntp < 4; ntp++) {
        float D[2][2][4];
        #pragma unroll
        for (int nn = 0; nn < 2; nn++) {
            int nt = 2 * ntp + nn;
            float b0 = b3v[nt * 8 + tig * 2];
            float b1 = b3v[nt * 8 + tig * 2 + 1];
            #pragma unroll
            for (int mt = 0; mt < 2; mt++) {
                D[mt][nn][0] = b0; D[mt][nn][1] = b1;
                D[mt][nn][2] = b0; D[mt][nn][3] = b1;
            }
        }
        #pragma unroll
        for (int nn = 0; nn < 2; nn++) {
            int nt = 2 * ntp + nn;
            #pragma unroll
            for (int kt = 0; kt < 4; kt++) {
                uint4 w = __ldg(&g_WF3[(nt * 4 + kt) * 32 + lane]);
                uint32_t bh[2] = { w.x, w.y };
                uint32_t bl[2] = { w.z, w.w };
                mma_h(D[0][nn], A3H[0][kt], bh);
                mma_h(D[0][nn], A3H[0][kt], bl);
                mma_h(D[1][nn], A3H[1][kt], bh);
                mma_h(D[1][nn], A3H[1][kt], bl);
            }
        }
        #pragma unroll
        for (int mt = 0; mt < 2; mt++) {
            #pragma unroll
            for (int nn = 0; nn < 2; nn++) {
                int nt = 2 * ntp + nn;
                int col = nt * 8 + tig * 2;
                float wa = w4v[col], wb = w4v[col + 1];
                dv[mt][0] = fmaf(siluf(D[mt][nn][0]), wa,
                            fmaf(siluf(D[mt][nn][1]), wb, dv[mt][0]));
                dv[mt][1] = fmaf(siluf(D[mt][nn][2]), wa,
                            fmaf(siluf(D[mt][nn][3]), wb, dv[mt][1]));
            }
        }
    }

    // ---- trans output ----
    #pragma unroll
    for (int mt = 0; mt < 2; mt++) {
        float d0 = dv[mt][0], d1 = dv[mt][1];
        d0 += __shfl_xor_sync(0xffffffffu, d0, 1);
        d0 += __shfl_xor_sync(0xffffffffu, d0, 2);
        d1 += __shfl_xor_sync(0xffffffffu, d1, 1);
        d1 += __shfl_xor_sync(0xffffffffu, d1, 2);
        int rw = mt * 16 + (tig & 1) * 8 + gid;
        float dsel = (tig & 1) ? d1 : d0;
        float rr  = __shfl_sync(0xffffffffu, r,  rw);
        float cxx = __shfl_sync(0xffffffffu, cx, rw);
        float cyy = __shfl_sync(0xffffffffu, cy, rw);
        float czz = __shfl_sync(0xffffffffu, cz, rw);
        int ee = base + m0 + rw;
        float msc = __fdividef(tanh_ap(dsel), sqrtf(rr) + 1e-8f);
        if (tig < 2 && ee < E) {
            outT[3 * ee + 0] = cxx * msc;
            outT[3 * ee + 1] = cyy * msc;
            outT[3 * ee + 2] = czz * msc;
        }
    }
}

extern "C" void kernel_launch(void* const* d_in, const int* in_sizes, int n_in,
                              void* d_out, int out_size) {
    const float* x  = (const float*)d_in[0];
    const float* hh = (const float*)d_in[1];
    const int* src  = (const int*)d_in[2];
    const int* dst  = (const int*)d_in[3];
    const float* W1 = (const float*)d_in[4];
    const float* b1 = (const float*)d_in[5];
    const float* W2 = (const float*)d_in[6];
    const float* b2 = (const float*)d_in[7];
    const float* W3 = (const float*)d_in[8];
    const float* b3 = (const float*)d_in[9];
    const float* W4 = (const float*)d_in[10];
    int N = in_sizes[0] / 3;
    int E = in_sizes[2];
    float* out = (float*)d_out;

    cudaFuncSetAttribute(precompute_mma_kernel,
                         cudaFuncAttributeMaxDynamicSharedMemorySize, SMEM_PRE);
    cudaFuncSetAttribute(edge_mma_kernel,
                         cudaFuncAttributeMaxDynamicSharedMemorySize, SMEM_EDG);

    pack_wf_kernel<<<8, 128>>>(W1, W2, W3);

    int pblocks = (N + 127) / 128;
    precompute_mma_kernel<<<pblocks, 128, SMEM_PRE>>>(x, hh, b1, N);

    int eblocks = (E + 127) / 128;
    edge_mma_kernel<<<eblocks, 128, SMEM_EDG>>>(src, dst, W1, b2, b3,
                                                W4, out, E);
    (void)n_in; (void)out_size;
}

// round 17
// speedup vs baseline: 1.0994x; 1.0117x over previous
#include <cuda_runtime.h>
#include <cuda_bf16.h>
#include <cuda_fp16.h>
#include <math.h>
#include <stdint.h>

// ---------------------------------------------------------------------------
// EGNN edge message via warp-level HMMA.  (r16 base + streaming output stores)
//   Kernel 0: pack W1a/W1b (bf16 hi/lo) + W2/W3 (fp16 hi/lo) fragment tables
//   Kernel 1: P[n] = [ hh[n]@W1a + b1 | hh[n]@W1b ] via HMMA (bf16 x3), fp16
//   Kernel 2 (per 128-edge block, 4 warps x 32 rows):
//     fp16 A tiles, fp16 hi/lo W (2 products), joint-mt W reuse;
//     pipelined layer-1 gather; f16x2 silu; outputs via st.global.cs so the
//     435MB output stream doesn't evict the 12.8MB P table from L2.
// Output: [ radial (E) | trans (3E) | edge_feature (64E) ]
// ---------------------------------------------------------------------------

#define N_MAX_NODES 50048
__device__ __half g_Ph[(size_t)N_MAX_NODES * 128];   // fp16 P table (256B/node)
__device__ float4 g_Xp[N_MAX_NODES];
__device__ uint4  g_WF1A[1024];   // bf16 hi/lo (precompute)
__device__ uint4  g_WF1B[1024];   // bf16 hi/lo (precompute)
__device__ uint4  g_WF2[1024];    // fp16 hi/lo (edge)
__device__ uint4  g_WF3[1024];    // fp16 hi/lo (edge)

__device__ __forceinline__ float tanh_ap(float v) {
    float t;
    asm("tanh.approx.f32 %0, %1;" : "=f"(t) : "f"(v));
    return t;
}
__device__ __forceinline__ float siluf(float v) {
    float t = 0.5f * v;
    return fmaf(t, tanh_ap(t), t);
}
__device__ __forceinline__ uint32_t hadd2u(uint32_t a, uint32_t b) {
    uint32_t d; asm("add.f16x2 %0,%1,%2;" : "=r"(d) : "r"(a), "r"(b)); return d;
}
__device__ __forceinline__ uint32_t hmul2u(uint32_t a, uint32_t b) {
    uint32_t d; asm("mul.f16x2 %0,%1,%2;" : "=r"(d) : "r"(a), "r"(b)); return d;
}
__device__ __forceinline__ uint32_t hfma2u(uint32_t a, uint32_t b, uint32_t c) {
    uint32_t d;
    asm("fma.rn.f16x2 %0,%1,%2,%3;" : "=r"(d) : "r"(a), "r"(b), "r"(c));
    return d;
}
__device__ __forceinline__ uint32_t silu_h2(uint32_t v) {
    uint32_t t = hmul2u(v, 0x38003800u);
    uint32_t th;
    asm("tanh.approx.f16x2 %0, %1;" : "=r"(th) : "r"(t));
    return hfma2u(t, th, t);
}

__device__ __forceinline__ void split_pair_bf(float a, float b,
                                              uint32_t& hi, uint32_t& lo) {
    __nv_bfloat162 h2 = __floats2bfloat162_rn(a, b);
    float ra = a - __bfloat162float(h2.x);
    float rb = b - __bfloat162float(h2.y);
    __nv_bfloat162 l2 = __floats2bfloat162_rn(ra, rb);
    hi = *reinterpret_cast<uint32_t*>(&h2);
    lo = *reinterpret_cast<uint32_t*>(&l2);
}

__device__ __forceinline__ void split_pair_h(float a, float b,
                                             uint32_t& hi, uint32_t& lo) {
    __half2 h2 = __floats2half2_rn(a, b);
    float ra = a - __half2float(__low2half(h2));
    float rb = b - __half2float(__high2half(h2));
    __half2 l2 = __floats2half2_rn(ra, rb);
    hi = *reinterpret_cast<uint32_t*>(&h2);
    lo = *reinterpret_cast<uint32_t*>(&l2);
}

__device__ __forceinline__ uint32_t packh2(float a, float b) {
    __half2 h2 = __floats2half2_rn(a, b);
    return *reinterpret_cast<uint32_t*>(&h2);
}

__device__ __forceinline__ float2 h2f2(uint32_t u) {
    return __half22float2(*reinterpret_cast<__half2*>(&u));
}

// streaming stores
__device__ __forceinline__ void stcs_f(float* p, float v) {
    asm volatile("st.global.cs.f32 [%0], %1;" :: "l"(p), "f"(v) : "memory");
}
__device__ __forceinline__ void stcs_f2(float* p, float a, float b) {
    asm volatile("st.global.cs.v2.f32 [%0], {%1,%2};"
                 :: "l"(p), "f"(a), "f"(b) : "memory");
}

// ---------------- Kernel 0: pack mma fragment tables -----------------------
__global__ void __launch_bounds__(128) pack_wf_kernel(
    const float* __restrict__ W1,
    const float* __restrict__ W2, const float* __restrict__ W3)
{
    int idx = blockIdx.x * 128 + threadIdx.x;
    if (idx >= 1024) return;
    int t = idx >> 5, l = idx & 31;
    int kt = t & 3, nt = t >> 2;
    int g = l >> 2, tg = l & 3;
    int k0 = kt * 16 + tg * 2;
    int n = nt * 8 + g;
    #pragma unroll
    for (int tab = 0; tab < 4; tab++) {
        const float* W;
        int roff = 0;
        uint4* dstv;
        if (tab == 0)      { W = W1; roff = 1;  dstv = g_WF1A; }
        else if (tab == 1) { W = W1; roff = 65; dstv = g_WF1B; }
        else if (tab == 2) { W = W2; dstv = g_WF2; }
        else               { W = W3; dstv = g_WF3; }
        float w00 = W[(roff + k0) * 64 + n],     w01 = W[(roff + k0 + 1) * 64 + n];
        float w10 = W[(roff + k0 + 8) * 64 + n], w11 = W[(roff + k0 + 9) * 64 + n];
        uint4 v;
        if (tab < 2) {
            split_pair_bf(w00, w01, v.x, v.z);
            split_pair_bf(w10, w11, v.y, v.w);
        } else {
            split_pair_h(w00, w01, v.x, v.z);
            split_pair_h(w10, w11, v.y, v.w);
        }
        dstv[idx] = v;
    }
}

// ------------------------------ mma helpers ---------------------------------
#define STS64(addr, v0, v1) \
    asm volatile("st.shared.v2.b32 [%0], {%1,%2};" \
                 :: "r"(addr), "r"(v0), "r"(v1) : "memory")
#define STS128(addr, v) \
    asm volatile("st.shared.v4.b32 [%0], {%1,%2,%3,%4};" \
                 :: "r"(addr), "r"((v).x), "r"((v).y), "r"((v).z), "r"((v).w) \
                 : "memory")

__device__ __forceinline__ void ldmx4(uint32_t* r, uint32_t addr) {
    asm volatile("ldmatrix.sync.aligned.m8n8.x4.shared.b16 {%0,%1,%2,%3}, [%4];"
        : "=r"(r[0]), "=r"(r[1]), "=r"(r[2]), "=r"(r[3]) : "r"(addr));
}

__device__ __forceinline__ void mma_bf(float* d, const uint32_t* a,
                                       const uint32_t* b) {
    asm volatile(
        "mma.sync.aligned.m16n8k16.row.col.f32.bf16.bf16.f32 "
        "{%0,%1,%2,%3}, {%4,%5,%6,%7}, {%8,%9}, {%0,%1,%2,%3};"
        : "+f"(d[0]), "+f"(d[1]), "+f"(d[2]), "+f"(d[3])
        : "r"(a[0]), "r"(a[1]), "r"(a[2]), "r"(a[3]), "r"(b[0]), "r"(b[1]));
}

__device__ __forceinline__ void mma_h(float* d, const uint32_t* a,
                                      const uint32_t* b) {
    asm volatile(
        "mma.sync.aligned.m16n8k16.row.col.f32.f16.f16.f32 "
        "{%0,%1,%2,%3}, {%4,%5,%6,%7}, {%8,%9}, {%0,%1,%2,%3};"
        : "+f"(d[0]), "+f"(d[1]), "+f"(d[2]), "+f"(d[3])
        : "r"(a[0]), "r"(a[1]), "r"(a[2]), "r"(a[3]), "r"(b[0]), "r"(b[1]));
}

// precompute smem layout (bf16 hi/lo, 128B rows x2)
#define PRE_AHI  0
#define PRE_ALO  16384
#define PRE_VEC  32768
#define SMEM_PRE 33792

// edge smem layout: fp16 A tile [0,16K), vectors
#define EDG_A    0
#define EDG_VEC  16384
#define SMEM_EDG 17408

// ---------------- Kernel 1: per-node projection via HMMA --------------------
__global__ void __launch_bounds__(128) precompute_mma_kernel(
    const float* __restrict__ x,
    const float* __restrict__ hh, const float* __restrict__ b1, int n_nodes)
{
    extern __shared__ char sm[];
    uint32_t smb = (uint32_t)__cvta_generic_to_shared(sm);
    int tid = threadIdx.x;
    int lane = tid & 31;
    int warp = tid >> 5;
    int m0 = warp * 32;
    int gid = lane >> 2, tig = lane & 3;

    float* b1v = (float*)(sm + PRE_VEC);
    if (tid < 64) b1v[tid] = b1[tid];

    int nb = blockIdx.x * 128;
    int node = nb + m0 + lane;
    if (node < n_nodes) {
        const float* xp = x + 3 * node;
        g_Xp[node] = make_float4(xp[0], xp[1], xp[2], 0.f);
    }

    uint32_t aHi = smb + PRE_AHI, aLo = smb + PRE_ALO;

    {
        int g = lane >> 3, c = lane & 7;
        #pragma unroll
        for (int j = 0; j < 8; j++) {
            int row = m0 + j * 4 + g;
            int n = nb + row;
            uint32_t rowHi = aHi + (uint32_t)row * 128;
            uint32_t rowLo = aLo + (uint32_t)row * 128;
            int rx = row & 7;
            #pragma unroll
            for (int half = 0; half < 2; half++) {
                int q = half * 8 + c;
                float4 a = (n < n_nodes)
                    ? *(const float4*)(hh + (size_t)n * 64 + q * 4)
                    : make_float4(0.f, 0.f, 0.f, 0.f);
                uint32_t hi0, lo0, hi1, lo1;
                split_pair_bf(a.x, a.y, hi0, lo0);
                split_pair_bf(a.z, a.w, hi1, lo1);
                uint32_t off = (uint32_t)((((q >> 1) ^ rx) << 4) + (q & 1) * 8);
                STS64(rowHi + off, hi0, hi1);
                STS64(rowLo + off, lo0, lo1);
            }
        }
    }
    __syncthreads();

    int Lmat = lane >> 3;
    #pragma unroll 1
    for (int mt = 0; mt < 2; mt++) {
        uint32_t AH[4][4], AL[4][4];
        #pragma unroll
        for (int kt = 0; kt < 4; kt++) {
            int rr = m0 + mt * 16 + (Lmat & 1) * 8 + (lane & 7);
            int chunk = kt * 2 + (Lmat >> 1);
            uint32_t off = (uint32_t)(rr * 128 + ((chunk ^ (rr & 7)) << 4));
            ldmx4(AH[kt], aHi + off);
            ldmx4(AL[kt], aLo + off);
        }
        int r0 = m0 + mt * 16 + gid;
        int r1 = r0 + 8;
        int n0 = nb + r0, n1 = nb + r1;

        #pragma unroll 1
        for (int half = 0; half < 2; half++) {
            const uint4* WF = half ? g_WF1B : g_WF1A;
            float D[8][4];
            #pragma unroll
            for (int nt = 0; nt < 8; nt++) {
                float b0 = half ? 0.f : b1v[nt * 8 + tig * 2];
                float b1x = half ? 0.f : b1v[nt * 8 + tig * 2 + 1];
                D[nt][0] = b0; D[nt][1] = b1x;
                D[nt][2] = b0; D[nt][3] = b1x;
            }
            #pragma unroll
            for (int nt = 0; nt < 8; nt++) {
                #pragma unroll
                for (int kt = 0; kt < 4; kt++) {
                    uint4 w = __ldg(&WF[(nt * 4 + kt) * 32 + lane]);
                    uint32_t bh[2] = { w.x, w.y };
                    uint32_t bl[2] = { w.z, w.w };
                    mma_bf(D[nt], AH[kt], bh);
                    mma_bf(D[nt], AH[kt], bl);
                    mma_bf(D[nt], AL[kt], bh);
                }
            }
            #pragma unroll
            for (int nt = 0; nt < 8; nt++) {
                int col = half * 64 + nt * 8 + tig * 2;
                if (n0 < n_nodes)
                    *(uint32_t*)((char*)g_Ph + (size_t)n0 * 256 + col * 2) =
                        packh2(D[nt][0], D[nt][1]);
                if (n1 < n_nodes)
                    *(uint32_t*)((char*)g_Ph + (size_t)n1 * 256 + col * 2) =
                        packh2(D[nt][2], D[nt][3]);
            }
        }
    }
}

// ---------------------------- Kernel 2: edges -------------------------------
__global__ void __launch_bounds__(128, 4) edge_mma_kernel(
    const int* __restrict__ src, const int* __restrict__ dst,
    const float* __restrict__ W1,
    const float* __restrict__ b2, const float* __restrict__ b3,
    const float* __restrict__ W4,
    float* __restrict__ out, int E)
{
    extern __shared__ char sm[];
    uint32_t smb = (uint32_t)__cvta_generic_to_shared(sm);
    int tid = threadIdx.x;
    int lane = tid & 31;
    int warp = tid >> 5;
    int m0 = warp * 32;
    int gid = lane >> 2, tig = lane & 3;

    uint32_t* w1h = (uint32_t*)(sm + EDG_VEC);        // packed f16x2 W1 row0
    float* b2v = (float*)(sm + EDG_VEC + 256);
    float* b3v = (float*)(sm + EDG_VEC + 512);
    float* w4v = (float*)(sm + EDG_VEC + 768);
    if (tid < 32) w1h[tid] = packh2(W1[2 * tid], W1[2 * tid + 1]);
    if (tid < 64) {
        b2v[tid] = b2[tid];
        b3v[tid] = b3[tid];
        w4v[tid] = W4[tid];
    }
    __syncthreads();

    int base = blockIdx.x * 128;
    int e = base + m0 + lane;
    bool valid = e < E;
    int s = 0, dn = 0;
    if (valid) { s = src[e]; dn = dst[e]; }
    float4 xs = g_Xp[s], xd = g_Xp[dn];
    float cx = xs.x - xd.x, cy = xs.y - xd.y, cz = xs.z - xd.z;
    float r = cx * cx + cy * cy + cz * cz;
    if (valid) stcs_f(out + e, r);

    uint32_t aT = smb + EDG_A;

    // ---- layer 1: pipelined fp16 P gather + f16x2 silu -> A tile ----
    {
        int g = lane >> 3, c = lane & 7;
        const char* Pb = (const char*)g_Ph;
        uint32_t wv0 = w1h[4 * c], wv1 = w1h[4 * c + 1],
                 wv2 = w1h[4 * c + 2], wv3 = w1h[4 * c + 3];

        int sE = __shfl_sync(0xffffffffu, s,  g);
        int dE = __shfl_sync(0xffffffffu, dn, g);
        float rE = __shfl_sync(0xffffffffu, r, g);
        uint4 av = *(const uint4*)(Pb + (size_t)sE * 256 + c * 16);
        uint4 bv = *(const uint4*)(Pb + (size_t)dE * 256 + 128 + c * 16);

        #pragma unroll
        for (int j = 0; j < 8; j++) {
            uint4 av2, bv2;
            float rEn = 0.f;
            if (j < 7) {
                int sl = (j + 1) * 4 + g;
                int sN = __shfl_sync(0xffffffffu, s,  sl);
                int dN = __shfl_sync(0xffffffffu, dn, sl);
                rEn = __shfl_sync(0xffffffffu, r, sl);
                av2 = *(const uint4*)(Pb + (size_t)sN * 256 + c * 16);
                bv2 = *(const uint4*)(Pb + (size_t)dN * 256 + 128 + c * 16);
            }
            uint32_t rE2 = packh2(rE, rE);
            int row = m0 + j * 4 + g;
            uint32_t rowB = aT + (uint32_t)row * 128;
            int rx = row & 7;
            uint4 hv;
            hv.x = silu_h2(hfma2u(rE2, wv0, hadd2u(av.x, bv.x)));
            hv.y = silu_h2(hfma2u(rE2, wv1, hadd2u(av.y, bv.y)));
            hv.z = silu_h2(hfma2u(rE2, wv2, hadd2u(av.z, bv.z)));
            hv.w = silu_h2(hfma2u(rE2, wv3, hadd2u(av.w, bv.w)));
            STS128(rowB + (uint32_t)(((c ^ rx) << 4)), hv);
            av = av2; bv = bv2; rE = rEn;
        }
    }
    __syncwarp();

    float* fout = out + (size_t)4 * E;
    float* outT = out + E;
    int Lmat = lane >> 3;

    // ---- A fragments for both 16-row halves (fp16 single) ----
    uint32_t AH[2][4][4];
    #pragma unroll
    for (int mt = 0; mt < 2; mt++) {
        #pragma unroll
        for (int kt = 0; kt < 4; kt++) {
            int rr = m0 + mt * 16 + (Lmat & 1) * 8 + (lane & 7);
            int chunk = kt * 2 + (Lmat >> 1);
            uint32_t off = (uint32_t)(rr * 128 + ((chunk ^ (rr & 7)) << 4));
            ldmx4(AH[mt][kt], aT + off);
        }
    }

    // ---- layer 2: joint-mt, nt pairs, W fetched once; f16x2 silu epilogue ----
    uint32_t A3H[2][4][4];
    #pragma unroll
    for (int ntp = 0; ntp < 4; ntp++) {
        float D[2][2][4];
        #pragma unroll
        for (int nn = 0; nn < 2; nn++) {
            int nt = 2 * ntp + nn;
            float b0 = b2v[nt * 8 + tig * 2];
            float b1 = b2v[nt * 8 + tig * 2 + 1];
            #pragma unroll
            for (int mt = 0; mt < 2; mt++) {
                D[mt][nn][0] = b0; D[mt][nn][1] = b1;
                D[mt][nn][2] = b0; D[mt][nn][3] = b1;
            }
        }
        #pragma unroll
        for (int nn = 0; nn < 2; nn++) {
            int nt = 2 * ntp + nn;
            #pragma unroll
            for (int kt = 0; kt < 4; kt++) {
                uint4 w = __ldg(&g_WF2[(nt * 4 + kt) * 32 + lane]);
                uint32_t bh[2] = { w.x, w.y };
                uint32_t bl[2] = { w.z, w.w };
                mma_h(D[0][nn], AH[0][kt], bh);
                mma_h(D[0][nn], AH[0][kt], bl);
                mma_h(D[1][nn], AH[1][kt], bh);
                mma_h(D[1][nn], AH[1][kt], bl);
            }
        }
        #pragma unroll
        for (int mt = 0; mt < 2; mt++) {
            int r0 = m0 + mt * 16 + gid;
            int r1 = r0 + 8;
            int e0 = base + r0, e1 = base + r1;
            #pragma unroll
            for (int nn = 0; nn < 2; nn++) {
                int nt = 2 * ntp + nn;
                uint32_t s01 = silu_h2(packh2(D[mt][nn][0], D[mt][nn][1]));
                uint32_t s23 = silu_h2(packh2(D[mt][nn][2], D[mt][nn][3]));
                int col = nt * 8 + tig * 2;
                if (e0 < E) {
                    float2 f = h2f2(s01);
                    stcs_f2(fout + (size_t)e0 * 64 + col, f.x, f.y);
                }
                if (e1 < E) {
                    float2 f = h2f2(s23);
                    stcs_f2(fout + (size_t)e1 * 64 + col, f.x, f.y);
                }
                A3H[mt][ntp][nn * 2 + 0] = s01;
                A3H[mt][ntp][nn * 2 + 1] = s23;
            }
        }
    }

    // ---- layer 3: joint-mt, dv accumulated per nt pair (fp32 epilogue) ----
    float dv[2][2] = { {0.f, 0.f}, {0.f, 0.f} };
    #pragma unroll
    for (int ntp = 0; ntp < 4; ntp++) {
        float D[2][2][4];
        #pragma unroll
        for (int nn = 0; nn < 2; nn++) {
            int nt = 2 * ntp + nn;
            float b0 = b3v[nt * 8 + tig * 2];
            float b1 = b3v[nt * 8 + tig * 2 + 1];
            #pragma unroll
            for (int mt = 0; mt < 2; mt++) {
                D[mt][nn][0] = b0; D[mt][nn][1] = b1;
                D[mt][nn][2] = b0; D[mt][nn][3] = b1;
            }
        }
        #pragma unroll
        for (int nn = 0; nn < 2; nn++) {
            int nt = 2 * ntp + nn;
            #pragma unroll
            for (int kt = 0; kt < 4; kt++) {
                uint4 w = __ldg(&g_WF3[(nt * 4 + kt) * 32 + lane]);
                uint32_t bh[2] = { w.x, w.y };
                uint32_t bl[2] = { w.z, w.w };
                mma_h(D[0][nn], A3H[0][kt], bh);
                mma_h(D[0][nn], A3H[0][kt], bl);
                mma_h(D[1][nn], A3H[1][kt], bh);
                mma_h(D[1][nn], A3H[1][kt], bl);
            }
        }
        #pragma unroll
        for (int mt = 0; mt < 2; mt++) {
            #pragma unroll
            for (int nn = 0; nn < 2; nn++) {
                int nt = 2 * ntp + nn;
                int col = nt * 8 + tig * 2;
                float wa = w4v[col], wb = w4v[col + 1];
                dv[mt][0] = fmaf(siluf(D[mt][nn][0]), wa,
                            fmaf(siluf(D[mt][nn][1]), wb, dv[mt][0]));
                dv[mt][1] = fmaf(siluf(D[mt][nn][2]), wa,
                            fmaf(siluf(D[mt][nn][3]), wb, dv[mt][1]));
            }
        }
    }

    // ---- trans output ----
    #pragma unroll
    for (int mt = 0; mt < 2; mt++) {
        float d0 = dv[mt][0], d1 = dv[mt][1];
        d0 += __shfl_xor_sync(0xffffffffu, d0, 1);
        d0 += __shfl_xor_sync(0xffffffffu, d0, 2);
        d1 += __shfl_xor_sync(0xffffffffu, d1, 1);
        d1 += __shfl_xor_sync(0xffffffffu, d1, 2);
        int rw = mt * 16 + (tig & 1) * 8 + gid;
        float dsel = (tig & 1) ? d1 : d0;
        float rr  = __shfl_sync(0xffffffffu, r,  rw);
        float cxx = __shfl_sync(0xffffffffu, cx, rw);
        float cyy = __shfl_sync(0xffffffffu, cy, rw);
        float czz = __shfl_sync(0xffffffffu, cz, rw);
        int ee = base + m0 + rw;
        float msc = __fdividef(tanh_ap(dsel), sqrtf(rr) + 1e-8f);
        if (tig < 2 && ee < E) {
            stcs_f(outT + 3 * ee + 0, cxx * msc);
            stcs_f(outT + 3 * ee + 1, cyy * msc);
            stcs_f(outT + 3 * ee + 2, czz * msc);
        }
    }
}

extern "C" void kernel_launch(void* const* d_in, const int* in_sizes, int n_in,
                              void* d_out, int out_size) {
    const float* x  = (const float*)d_in[0];
    const float* hh = (const float*)d_in[1];
    const int* src  = (const int*)d_in[2];
    const int* dst  = (const int*)d_in[3];
    const float* W1 = (const float*)d_in[4];
    const float* b1 = (const float*)d_in[5];
    const float* W2 = (const float*)d_in[6];
    const float* b2 = (const float*)d_in[7];
    const float* W3 = (const float*)d_in[8];
    const float* b3 = (const float*)d_in[9];
    const float* W4 = (const float*)d_in[10];
    int N = in_sizes[0] / 3;
    int E = in_sizes[2];
    float* out = (float*)d_out;

    cudaFuncSetAttribute(precompute_mma_kernel,
                         cudaFuncAttributeMaxDynamicSharedMemorySize, SMEM_PRE);
    cudaFuncSetAttribute(edge_mma_kernel,
                         cudaFuncAttributeMaxDynamicSharedMemorySize, SMEM_EDG);

    pack_wf_kernel<<<8, 128>>>(W1, W2, W3);

    int pblocks = (N + 127) / 128;
    precompute_mma_kernel<<<pblocks, 128, SMEM_PRE>>>(x, hh, b1, N);

    int eblocks = (E + 127) / 128;
    edge_mma_kernel<<<eblocks, 128, SMEM_EDG>>>(src, dst, W1, b2, b3,
                                                W4, out, E);
    (void)n_in; (void)out_size;
}